// round 16
// baseline (speedup 1.0000x reference)
#include <cuda_runtime.h>
#include <math.h>
#include <stdint.h>
#include <stddef.h>

#define B_    16
#define T_    257
#define H_    1024
#define V_    1024
#define S_    512
#define E_    512
#define ENC2_ 1024
#define SOS_  1
#define EOS_  2
#define NCTA  128
#define NTHR  512

#define XROW  1032                  // padded xs row stride (floats): banks 0/8/16/24
#define GROW  20                    // padded gp row stride (floats)

typedef unsigned long long u64;
static const size_t MSZ = 128ull * 256 * 32 * 4;   // floats per packed matrix

// ---------------------------------------------------------------------------
// f32x2 packed-math helpers
// ---------------------------------------------------------------------------
__device__ __forceinline__ u64 pack2(float v) {
    u64 r; asm("mov.b64 %0, {%1, %1};" : "=l"(r) : "f"(v)); return r;
}
__device__ __forceinline__ void ffma2(u64& d, u64 a, u64 b) {
    asm("fma.rn.f32x2 %0, %1, %2, %0;" : "+l"(d) : "l"(a), "l"(b));
}
__device__ __forceinline__ float2 unpack2(u64 v) {
    float2 f; asm("mov.b64 {%0, %1}, %2;" : "=f"(f.x), "=f"(f.y) : "l"(v)); return f;
}

// cp.async: stage 64KB h[16][1024] into padded xs[16][XROW] with 512 threads
__device__ __forceinline__ void stage_async(const float* __restrict__ src,
                                            float* __restrict__ dst, int tid) {
#pragma unroll
    for (int i = 0; i < 8; ++i) {
        int g = tid + NTHR * i;                  // float4 index in [0,4096)
        int row = g >> 8, col4 = g & 255;
        unsigned u = (unsigned)__cvta_generic_to_shared(dst + row * XROW + col4 * 4);
        asm volatile("cp.async.cg.shared.global [%0], [%1], 16;"
                     :: "r"(u), "l"(src + (size_t)g * 4));
    }
    asm volatile("cp.async.commit_group;");
}
template <int N> __device__ __forceinline__ void cp_wait() {
    asm volatile("cp.async.wait_group %0;" :: "n"(N));
}

// ---------------------------------------------------------------------------
// Device scratch (static only)
// ---------------------------------------------------------------------------
__device__ float d_P0[(size_t)V_ * 4096];                 // 16 MB
__device__ float d_Wp[5ull * 128 * 256 * 32 * 4];         // 80 MB packed panels
__device__ float d_h[3][2][B_ * H_];                      // h, batch-major [b][col]
__device__ float d_hs[(size_t)B_ * T_ * H_];
__device__ float d_scores[(size_t)B_ * T_ * S_];
__device__ float d_ctx[(size_t)B_ * T_ * H_];
__device__ float d_hidden[(size_t)B_ * T_ * H_];
__device__ float d_logits[(size_t)B_ * T_ * V_];
__device__ float d_nll[B_ * T_];
__device__ unsigned d_bar_cnt;
__device__ volatile unsigned d_bar_gen;

// ---------------------------------------------------------------------------
// Fused pack (5 matrices) + state init. grid (128, 8, 5).
// out[m][((cta*256 + k4)*32 + p)*4 + kk] = W[(p>>3)*1024 + cta*8 + (p&7)][k4*4+kk]
// ---------------------------------------------------------------------------
__global__ void pack5init_k(const float* __restrict__ Wa, const float* __restrict__ Wb,
                            const float* __restrict__ Wc, const float* __restrict__ Wd,
                            const float* __restrict__ We, float* __restrict__ out) {
    const int z = blockIdx.z;
    const float* W = (z == 0) ? Wa : (z == 1) ? Wb : (z == 2) ? Wc : (z == 3) ? Wd : We;
    float* o = out + (size_t)z * MSZ;
    const int cta = blockIdx.x, kb = blockIdx.y;   // 128 x 8
    const int lane = threadIdx.x & 31, kq = threadIdx.x >> 5;
    const int j = (lane >> 3) * 1024 + cta * 8 + (lane & 7);
#pragma unroll
    for (int i = 0; i < 4; ++i) {
        int k4 = kb * 32 + kq * 4 + i;
        float4 v = *(const float4*)(W + (size_t)j * 1024 + k4 * 4);
        *(float4*)(o + (((size_t)cta * 256 + k4) * 32 + lane) * 4) = v;
    }
    if (z == 0 && kb == 0) {                       // init: 128 blocks x 256 thr
        int i = cta * 256 + threadIdx.x;
        if (i == 0) { d_bar_cnt = 0; d_bar_gen = 0; }
        float* h = &d_h[0][0][0];
        const int n = 3 * 2 * B_ * H_;
        for (int jj = i; jj < n; jj += 128 * 256) h[jj] = 0.f;
    }
}

// ---------------------------------------------------------------------------
__device__ __forceinline__ void gridsync(unsigned& lgen) {
    __syncthreads();
    if (threadIdx.x == 0) {
        __threadfence();
        unsigned target = ++lgen;
        unsigned arrived = atomicAdd(&d_bar_cnt, 1u) + 1u;
        if (arrived == target * (unsigned)NCTA) {
            d_bar_gen = target;
        } else {
            while (d_bar_gen < target) { __nanosleep(32); }
        }
        __threadfence();
    }
    __syncthreads();
}

__device__ __forceinline__ float sigmoidf_(float x) { return 1.f / (1.f + __expf(-x)); }

// ---------------------------------------------------------------------------
// k-paired accumulate: lane owns rows {p0, p0+1}, batches {bgrp, 4+bgrp, 8+bgrp,
// 12+bgrp}, k-slice [kq*128, kq*128+128). acc[j] u64 = (even-k sum, odd-k sum).
// W fed as u64 k-pairs straight from the panel (no duplication MOVs).
// ---------------------------------------------------------------------------
__device__ __forceinline__ void accum2(const float* __restrict__ Wm, int cta,
                                       int kq, int p0, int bgrp,
                                       const float* __restrict__ xs, u64 acc[8]) {
    const ulonglong2* wp = (const ulonglong2*)Wm
                         + (((size_t)cta * 256 + (size_t)kq * 32) * 32 + p0);
    const float* x0 = xs + (bgrp     ) * XROW + kq * 128;
    const float* x1 = xs + (bgrp +  4) * XROW + kq * 128;
    const float* x2 = xs + (bgrp +  8) * XROW + kq * 128;
    const float* x3 = xs + (bgrp + 12) * XROW + kq * 128;
#pragma unroll 4
    for (int s = 0; s < 32; ++s) {
        ulonglong2 w0 = wp[s * 32];          // row p0:   (w[k],w[k+1]),(w[k+2],w[k+3])
        ulonglong2 w1 = wp[s * 32 + 1];      // row p0+1
        ulonglong2 a = *(const ulonglong2*)(x0 + s * 4);
        ulonglong2 b = *(const ulonglong2*)(x1 + s * 4);
        ulonglong2 c = *(const ulonglong2*)(x2 + s * 4);
        ulonglong2 d = *(const ulonglong2*)(x3 + s * 4);
        ffma2(acc[0], w0.x, a.x); ffma2(acc[0], w0.y, a.y);
        ffma2(acc[1], w0.x, b.x); ffma2(acc[1], w0.y, b.y);
        ffma2(acc[2], w0.x, c.x); ffma2(acc[2], w0.y, c.y);
        ffma2(acc[3], w0.x, d.x); ffma2(acc[3], w0.y, d.y);
        ffma2(acc[4], w1.x, a.x); ffma2(acc[4], w1.y, a.y);
        ffma2(acc[5], w1.x, b.x); ffma2(acc[5], w1.y, b.y);
        ffma2(acc[6], w1.x, c.x); ffma2(acc[6], w1.y, c.y);
        ffma2(acc[7], w1.x, d.x); ffma2(acc[7], w1.y, d.y);
    }
}

__device__ __forceinline__ void zero8(u64 acc[8]) {
#pragma unroll
    for (int p = 0; p < 8; ++p) acc[p] = 0ull;
}

// fold k-pair halves and scatter to gp[kq][row][b]
__device__ __forceinline__ void dump2(float* __restrict__ gp, int kq, int p0, int bgrp,
                                      const u64 acc[8]) {
    float* g0 = gp + (kq * 32 + p0) * GROW;
    float* g1 = g0 + GROW;
#pragma unroll
    for (int i = 0; i < 4; ++i) {
        float2 u = unpack2(acc[i]);     g0[i * 4 + bgrp] = u.x + u.y;
        float2 v = unpack2(acc[4 + i]); g1[i * 4 + bgrp] = v.x + v.y;
    }
}

// sum of 8 k-warp partials for row, batch bb
__device__ __forceinline__ float gate_sum(const float* __restrict__ gp, int row, int bb) {
    float s = 0.f;
#pragma unroll
    for (int k = 0; k < 8; ++k) s += gp[(k * 32 + row) * GROW + bb];
    return s;
}

// quad shuffle butterfly -> full i,f,g,o per lane; gate-0 lane writes state
__device__ __forceinline__ void lstm_update(float s, int gate, float* __restrict__ cptr,
                                            float* __restrict__ h1,
                                            float* __restrict__ h2) {
    float b1v = __shfl_xor_sync(0xffffffffu, s,   1);
    float c2v = __shfl_xor_sync(0xffffffffu, s,   2);
    float d2v = __shfl_xor_sync(0xffffffffu, b1v, 2);
    float g0, g1, g2, g3;
    if      (gate == 0) { g0 = s;   g1 = b1v; g2 = c2v; g3 = d2v; }
    else if (gate == 1) { g0 = b1v; g1 = s;   g2 = d2v; g3 = c2v; }
    else if (gate == 2) { g0 = c2v; g1 = d2v; g2 = s;   g3 = b1v; }
    else                { g0 = d2v; g1 = c2v; g2 = b1v; g3 = s;   }
    float ig = sigmoidf_(g0), fg = sigmoidf_(g1);
    float gt = tanhf(g2),     og = sigmoidf_(g3);
    float cc = fg * (*cptr) + ig * gt;
    float hh = og * tanhf(cc);
    if (gate == 0) {
        *cptr = cc;
        *h1 = hh;
        if (h2) *h2 = hh;
    }
}

// ---------------------------------------------------------------------------
// Persistent LSTM recurrence, wavefront-pipelined, k-paired FFMA2.
// smem (floats): xs0[16512] xs1[16512] gpA[5120] gpB[5120] c_s[384] = 43648 (~171KB)
// ---------------------------------------------------------------------------
__global__ __launch_bounds__(NTHR, 1) void recur_k(const int* __restrict__ tokens,
    const float* __restrict__ bih1, const float* __restrict__ bhh1,
    const float* __restrict__ bih2, const float* __restrict__ bhh2) {

    extern __shared__ float smem[];
    float* xs0 = smem;                       // 16512
    float* xs1 = smem + 16512;               // 16512
    float* gpA = smem + 33024;               // 5120
    float* gpB = smem + 38144;               // 5120
    float* c_s = smem + 43264;               // 384

    const int tid = threadIdx.x, cta = blockIdx.x;
    for (int i = tid; i < 384; i += NTHR) c_s[i] = 0.f;

    // GEMM mapping
    const int warp = tid >> 5, lane = tid & 31;
    const int kq = warp >> 1, rhalf = warp & 1;
    const int rg = lane >> 2, bgrp = lane & 3;
    const int p0 = (rhalf * 8 + rg) * 2;

    // update mapping
    const int quad = tid >> 2, gate = tid & 3;
    const int uu = quad >> 4, bb = quad & 15;
    const int ucol = cta * 8 + uu;
    const int row = gate * 8 + uu;
    const int jb = gate * 1024 + ucol;

    const float bL1 = bih1[jb] + bhh1[jb];
    const float bL2 = bih2[jb] + bhh2[jb];

    const float* W0 = d_Wp;                 // Whh0
    const float* W1 = d_Wp + 1 * MSZ;       // Wih1
    const float* W2 = d_Wp + 2 * MSZ;       // Whh1
    const float* W3 = d_Wp + 3 * MSZ;       // Wih2
    const float* W4 = d_Wp + 4 * MSZ;       // Whh2

    unsigned lgen = 0;
    __syncthreads();

    u64 acc[8];

    // prologue: h0(-1), h1(-1) are zeros in buffer 0
    stage_async(d_h[0][0], xs0, tid);
    stage_async(d_h[1][0], xs1, tid);

    for (int w = 0; w < T_ + 2; ++w) {
        const int rb = w & 1, wb = rb ^ 1;
        const bool L0 = (w < T_);              // layer0 time w
        const bool L1 = (w >= 1) && (w <= T_); // layer1 time w-1
        const bool L2 = (w >= 2);              // layer2 time w-2

        cp_wait<1>(); __syncthreads();          // xs0 = h0 ready

        if (L0) { zero8(acc); accum2(W0, cta, kq, p0, bgrp, xs0, acc);
                  dump2(gpA, kq, p0, bgrp, acc); }
        if (L1) { zero8(acc); accum2(W1, cta, kq, p0, bgrp, xs0, acc); }
        __syncthreads();                        // xs0 consumed, gpA visible
        stage_async(d_h[2][rb], xs0, tid);      // h2 -> xs0

        cp_wait<1>(); __syncthreads();          // xs1 = h1 ready
        if (L1) { accum2(W2, cta, kq, p0, bgrp, xs1, acc);
                  dump2(gpB, kq, p0, bgrp, acc); }
        __syncthreads();                        // gpB visible

        // ---- L0 + L1 updates ----
        if (L0) {
            int tok = (w == 0) ? SOS_ : tokens[bb * 256 + (w - 1)];
            float s = gate_sum(gpA, row, bb) + d_P0[(size_t)tok * 4096 + jb];
            lstm_update(s, gate, &c_s[uu * 16 + bb],
                        &d_h[0][wb][bb * H_ + ucol], nullptr);
        }
        if (L1) {
            float s = gate_sum(gpB, row, bb) + bL1;
            lstm_update(s, gate, &c_s[128 + uu * 16 + bb],
                        &d_h[1][wb][bb * H_ + ucol], nullptr);
        }
        __syncthreads();                        // gpA reads done

        if (L2) { zero8(acc); accum2(W3, cta, kq, p0, bgrp, xs1, acc); }
        cp_wait<0>(); __syncthreads();          // xs0 = h2 ready (xs1 consumed)
        if (L2) { accum2(W4, cta, kq, p0, bgrp, xs0, acc);
                  dump2(gpA, kq, p0, bgrp, acc); }
        __syncthreads();

        if (L2) {
            int u = w - 2;
            float s = gate_sum(gpA, row, bb) + bL2;
            lstm_update(s, gate, &c_s[256 + uu * 16 + bb],
                        &d_h[2][wb][bb * H_ + ucol],
                        &d_hs[((size_t)bb * T_ + u) * H_ + ucol]);
        }

        gridsync(lgen);                         // ONE barrier per wave

        if (w + 1 < T_ + 2) {
            stage_async(d_h[0][wb], xs0, tid);  // next wave h0
            stage_async(d_h[1][wb], xs1, tid);  // next wave h1
        }
    }
}

// ---------------------------------------------------------------------------
// Tiled SGEMM with f32x2 micro-kernel. TRANSB=1: C = A * B^T ; else C = A * B
// ---------------------------------------------------------------------------
template <int TRANSB, int ACCUM, int DOTANH>
__global__ void gemm_k(const float* __restrict__ A, const float* __restrict__ B,
                       float* __restrict__ C,
                       int M, int N, int K, int lda, int ldb, int ldc,
                       long long sA, long long sB, long long sC,
                       const float* __restrict__ bias1,
                       const float* __restrict__ bias2) {
    A += (long long)blockIdx.z * sA;
    B += (long long)blockIdx.z * sB;
    C += (long long)blockIdx.z * sC;

    __shared__ float As[16][68];
    __shared__ float Bs[16][68];

    const int m0 = blockIdx.y * 64, n0 = blockIdx.x * 64;
    const int tid = threadIdx.x;
    const int ty = tid >> 4, tx = tid & 15;
    const int lr = tid >> 2;
    const int lk = (tid & 3) << 2;

    u64 acc2[4][2] = {};

    for (int kt = 0; kt < K; kt += 16) {
        float4 av = make_float4(0.f, 0.f, 0.f, 0.f);
        if (m0 + lr < M) av = *(const float4*)(A + (size_t)(m0 + lr) * lda + kt + lk);
        As[lk + 0][lr] = av.x; As[lk + 1][lr] = av.y;
        As[lk + 2][lr] = av.z; As[lk + 3][lr] = av.w;
        if (TRANSB) {
            float4 bv = *(const float4*)(B + (size_t)(n0 + lr) * ldb + kt + lk);
            Bs[lk + 0][lr] = bv.x; Bs[lk + 1][lr] = bv.y;
            Bs[lk + 2][lr] = bv.z; Bs[lk + 3][lr] = bv.w;
        } else {
            int bk = tid >> 4, bn = (tid & 15) << 2;
            float4 bv = *(const float4*)(B + (size_t)(kt + bk) * ldb + n0 + bn);
            *(float4*)&Bs[bk][bn] = bv;
        }
        __syncthreads();
#pragma unroll
        for (int kk = 0; kk < 16; ++kk) {
            float4 a = *(const float4*)&As[kk][ty << 2];
            ulonglong2 b2 = *(const ulonglong2*)&Bs[kk][tx << 2];
            u64 a0 = pack2(a.x), a1 = pack2(a.y), a2 = pack2(a.z), a3 = pack2(a.w);
            ffma2(acc2[0][0], a0, b2.x); ffma2(acc2[0][1], a0, b2.y);
            ffma2(acc2[1][0], a1, b2.x); ffma2(acc2[1][1], a1, b2.y);
            ffma2(acc2[2][0], a2, b2.x); ffma2(acc2[2][1], a2, b2.y);
            ffma2(acc2[3][0], a3, b2.x); ffma2(acc2[3][1], a3, b2.y);
        }
        __syncthreads();
    }

#pragma unroll
    for (int i = 0; i < 4; ++i) {
        int m = m0 + (ty << 2) + i;
        if (m >= M) continue;
        float vj[4];
        float2 u0 = unpack2(acc2[i][0]), u1 = unpack2(acc2[i][1]);
        vj[0] = u0.x; vj[1] = u0.y; vj[2] = u1.x; vj[3] = u1.y;
#pragma unroll
        for (int j = 0; j < 4; ++j) {
            int n = n0 + (tx << 2) + j;
            float v = vj[j];
            if (ACCUM) v += C[(size_t)m * ldc + n];
            if (bias1) v += bias1[n];
            if (bias2) v += bias2[n];
            if (DOTANH) v = tanhf(v);
            C[(size_t)m * ldc + n] = v;
        }
    }
}

// ---------------------------------------------------------------------------
__global__ void softmax_k() {
    __shared__ float red[256];
    const int tid = threadIdx.x;
    float* x = d_scores + (size_t)blockIdx.x * S_;
    float m = fmaxf(x[tid], x[tid + 256]);
    red[tid] = m; __syncthreads();
    for (int s = 128; s > 0; s >>= 1) {
        if (tid < s) red[tid] = fmaxf(red[tid], red[tid + s]);
        __syncthreads();
    }
    m = red[0]; __syncthreads();
    float e0 = __expf(x[tid] - m), e1 = __expf(x[tid + 256] - m);
    red[tid] = e0 + e1; __syncthreads();
    for (int s = 128; s > 0; s >>= 1) {
        if (tid < s) red[tid] += red[tid + s];
        __syncthreads();
    }
    float inv = 1.f / red[0];
    x[tid] = e0 * inv;
    x[tid + 256] = e1 * inv;
}

__global__ void nll_k(const int* __restrict__ tokens) {
    __shared__ float red[256];
    const int tid = threadIdx.x;
    const int row = blockIdx.x;
    const int b = row / T_, t = row % T_;
    const float* x = d_logits + (size_t)row * V_;
    float m = -1e30f;
    for (int i = tid; i < V_; i += 256) m = fmaxf(m, x[i]);
    red[tid] = m; __syncthreads();
    for (int s = 128; s > 0; s >>= 1) {
        if (tid < s) red[tid] = fmaxf(red[tid], red[tid + s]);
        __syncthreads();
    }
    m = red[0]; __syncthreads();
    float sum = 0.f;
    for (int i = tid; i < V_; i += 256) sum += __expf(x[i] - m);
    red[tid] = sum; __syncthreads();
    for (int s = 128; s > 0; s >>= 1) {
        if (tid < s) red[tid] += red[tid + s];
        __syncthreads();
    }
    if (tid == 0) {
        int tgt = (t < 256) ? tokens[b * 256 + t] : EOS_;
        d_nll[row] = m + logf(red[0]) - x[tgt];
    }
}

__global__ void mean_k(float* __restrict__ out) {
    __shared__ float red[256];
    const int tid = threadIdx.x;
    float s = 0.f;
    for (int i = tid; i < B_ * T_; i += 256) s += d_nll[i];
    red[tid] = s; __syncthreads();
    for (int st = 128; st > 0; st >>= 1) {
        if (tid < st) red[tid] += red[tid + st];
        __syncthreads();
    }
    if (tid == 0) out[0] = red[0] / (float)(B_ * T_);
}

// ---------------------------------------------------------------------------
extern "C" void kernel_launch(void* const* d_in, const int* in_sizes, int n_in,
                              void* d_out, int out_size) {
    const int*   tokens = (const int*)  d_in[0];
    const float* enc    = (const float*)d_in[1];
    const float* emb    = (const float*)d_in[2];
    const float* Wih0   = (const float*)d_in[3];
    const float* Whh0   = (const float*)d_in[4];
    const float* bih0   = (const float*)d_in[5];
    const float* bhh0   = (const float*)d_in[6];
    const float* Wih1   = (const float*)d_in[7];
    const float* Whh1   = (const float*)d_in[8];
    const float* bih1   = (const float*)d_in[9];
    const float* bhh1   = (const float*)d_in[10];
    const float* Wih2   = (const float*)d_in[11];
    const float* Whh2   = (const float*)d_in[12];
    const float* bih2   = (const float*)d_in[13];
    const float* bhh2   = (const float*)d_in[14];
    const float* W1     = (const float*)d_in[15];
    const float* b1     = (const float*)d_in[16];
    const float* W2     = (const float*)d_in[17];
    const float* b2     = (const float*)d_in[18];
    float* out = (float*)d_out;

    float* P0;      cudaGetSymbolAddress((void**)&P0,      d_P0);
    float* Wp;      cudaGetSymbolAddress((void**)&Wp,      d_Wp);
    float* hs;      cudaGetSymbolAddress((void**)&hs,      d_hs);
    float* scores;  cudaGetSymbolAddress((void**)&scores,  d_scores);
    float* ctx;     cudaGetSymbolAddress((void**)&ctx,     d_ctx);
    float* hidden;  cudaGetSymbolAddress((void**)&hidden,  d_hidden);
    float* logits;  cudaGetSymbolAddress((void**)&logits,  d_logits);

    const int RSMEM = 43648 * 4;   // ~171 KB
    static int smem_set = 0;
    if (!smem_set) {
        cudaFuncSetAttribute(recur_k, cudaFuncAttributeMaxDynamicSharedMemorySize, RSMEM);
        smem_set = 1;
    }

    // P0 = emb @ Wih0[:, :E]^T + bih0 + bhh0   (two N-halves)
    gemm_k<1,0,0><<<dim3(32, 16, 1), 256>>>(                      // 0
        emb, Wih0, P0, 1024, 2048, 512, 512, 1536, 4096, 0, 0, 0, bih0, bhh0);
    gemm_k<1,0,0><<<dim3(32, 16, 1), 256>>>(                      // 1
        emb, Wih0 + 2048ll * 1536, P0 + 2048, 1024, 2048, 512, 512, 1536, 4096,
        0, 0, 0, bih0 + 2048, bhh0 + 2048);
    // pack all 5 recurrent matrices + init state/barrier
    pack5init_k<<<dim3(128, 8, 5), 256>>>(Whh0, Wih1, Whh1, Wih2, Whh2, Wp);  // 2

    // persistent wavefront recurrence (launch index 3)
    recur_k<<<NCTA, NTHR, RSMEM>>>(tokens, bih1, bhh1, bih2, bhh2);           // 3

    // attention scores: [b] hs[257,1024] * enc[512,1024]^T
    gemm_k<1,0,0><<<dim3(8, 5, 16), 256>>>(
        hs, enc, scores, T_, S_, H_, H_, ENC2_, S_,
        (long long)T_ * H_, (long long)S_ * ENC2_, (long long)T_ * S_,
        nullptr, nullptr);

    softmax_k<<<B_ * T_, 256>>>();

    // context: [b] probs[257,512] * enc[512,1024]
    gemm_k<0,0,0><<<dim3(16, 5, 16), 256>>>(
        scores, enc, ctx, T_, ENC2_, S_, S_, ENC2_, ENC2_,
        (long long)T_ * S_, (long long)S_ * ENC2_, (long long)T_ * ENC2_,
        nullptr, nullptr);

    // hidden = tanh(hs @ W1[:, :H]^T + ctx @ W1[:, H:]^T + b1)
    gemm_k<1,0,0><<<dim3(16, 65, 1), 256>>>(
        hs, W1, hidden, B_ * T_, H_, H_, H_, 2048, H_, 0, 0, 0,
        nullptr, nullptr);
    gemm_k<1,1,1><<<dim3(16, 65, 1), 256>>>(
        ctx, W1 + 1024, hidden, B_ * T_, H_, ENC2_, ENC2_, 2048, H_, 0, 0, 0,
        b1, nullptr);

    // logits = hidden @ W2^T + b2
    gemm_k<1,0,0><<<dim3(16, 65, 1), 256>>>(
        hidden, W2, logits, B_ * T_, V_, H_, H_, H_, V_, 0, 0, 0,
        b2, nullptr);

    nll_k<<<B_ * T_, 256>>>(tokens);
    mean_k<<<1, 256>>>(out);
}